// round 15
// baseline (speedup 1.0000x reference)
#include <cuda_runtime.h>
#include <cuda_fp16.h>
#include <cstdint>

// Problem constants
#define BB   8
#define FI   512
#define FO   512
#define HH   64
#define WW   64
#define DSTYLE 512
#define KTOT 4608                // 9 * 512

#define FC_SCALE 0.04419417382415922f      // 512^-0.5
#define W_SCALE  0.014731391274719739f     // (512*9)^-0.5
#define EPSI     1e-8f

// GEMM pipeline config
#define NSTG        5
#define ROWB        80           // 64B data + 16B pad -> conflict-free ldmatrix, no swizzle
#define A_BYTES     (128*ROWB)   // 10240
#define B_BYTES     (128*ROWB)   // 10240
#define STAGE_BYTES (A_BYTES + B_BYTES)        // 20480
#define SMEM_TOTAL  (NSTG*STAGE_BYTES)         // 102400 per CTA (2 CTAs/SM)
#define NCHUNK      144          // 9 kk * 16 fi-chunks of 32

// Scratch (device globals; no allocation allowed)
__device__ float  g_s[BB*FI];
__device__ float  g_d[BB*FO];
__device__ __half g_wh[(size_t)FO*KTOT];     // w_hi  [fo][kk*512+fi]
__device__ __half g_xh[(size_t)BB*HH*WW*FI]; // xm_hi [b][r][c][fi]

// ---------------------------------------------------------------------------
// helpers
// ---------------------------------------------------------------------------
__device__ __forceinline__ uint32_t smem_u32(const void* p){
    uint32_t a;
    asm("{ .reg .u64 t; cvta.to.shared.u64 t, %1; cvt.u32.u64 %0, t; }"
        : "=r"(a) : "l"(p));
    return a;
}
__device__ __forceinline__ void cp16(uint32_t dst, const void* src, int srcsz){
    asm volatile("cp.async.cg.shared.global [%0], [%1], 16, %2;"
                 :: "r"(dst), "l"(src), "r"(srcsz) : "memory");
}
#define CP_COMMIT() asm volatile("cp.async.commit_group;" ::: "memory")
#define CP_WAIT3()  asm volatile("cp.async.wait_group 3;" ::: "memory")

#define LDSM4(r, addr) \
    asm volatile("ldmatrix.sync.aligned.m8n8.x4.shared.b16 {%0,%1,%2,%3}, [%4];" \
        : "=r"((r)[0]),"=r"((r)[1]),"=r"((r)[2]),"=r"((r)[3]) : "r"(addr))

__device__ __forceinline__ void mma16816(float* c, const uint32_t* a,
                                         uint32_t b0, uint32_t b1){
    asm volatile("mma.sync.aligned.m16n8k16.row.col.f32.f16.f16.f32 "
        "{%0,%1,%2,%3}, {%4,%5,%6,%7}, {%8,%9}, {%0,%1,%2,%3};"
        : "+f"(c[0]),"+f"(c[1]),"+f"(c[2]),"+f"(c[3])
        : "r"(a[0]),"r"(a[1]),"r"(a[2]),"r"(a[3]), "r"(b0),"r"(b1));
}
__device__ __forceinline__ void stcs(float* p, float v){
    asm volatile("st.global.cs.f32 [%0], %1;" :: "l"(p), "f"(v) : "memory");
}

// ---------------------------------------------------------------------------
// Kernel 1: s[b,i] = fc_b[i] + fc_scale * sum_j style[b,j] * fc_w[i,j]
// ---------------------------------------------------------------------------
__global__ void k_style(const float* __restrict__ style,
                        const float* __restrict__ fc_w,
                        const float* __restrict__ fc_b) {
    int b = blockIdx.x;
    __shared__ float st[DSTYLE];
    for (int j = threadIdx.x; j < DSTYLE; j += blockDim.x)
        st[j] = style[b * DSTYLE + j];
    __syncthreads();
    for (int i = threadIdx.x; i < FI; i += blockDim.x) {
        const float* wr = fc_w + (size_t)i * DSTYLE;
        float acc = 0.f;
        #pragma unroll 8
        for (int j = 0; j < DSTYLE; ++j) acc += st[j] * wr[j];
        g_s[b * FI + i] = acc * FC_SCALE + fc_b[i];
    }
}

// ---------------------------------------------------------------------------
// Kernel 2 (fused): per fo-row (one block each):
//   - stage w row [fi*9] in smem (one coalesced read of w)
//   - write g_wh[fo][kk*512+fi] coalesced (stride-9 smem reads, conflict-free)
//   - wsq[fi] = sum_k w^2;  d[b,fo] = rsqrt(ws^2 * sum_fi wsq*s^2 + eps)
// ---------------------------------------------------------------------------
__global__ void k_wd(const float* __restrict__ w) {
    __shared__ float row[KTOT];              // 4608 floats = 18KB
    __shared__ float red[BB][128];
    int fo = blockIdx.x;
    int t  = threadIdx.x;                    // 128 threads
    const float* src = w + (size_t)fo * KTOT;
    for (int i = t; i < KTOT; i += 128)
        row[i] = src[i];
    __syncthreads();

    // transposed fp16 write (coalesced out; stride-9 smem: gcd(9,32)=1 -> no conflicts)
    __half* dst = g_wh + (size_t)fo * KTOT;
    for (int i = t; i < KTOT; i += 128) {
        int kk = i >> 9, fi = i & 511;
        dst[i] = __float2half(row[fi * 9 + kk] * W_SCALE);
    }

    // demod partials: each thread handles 4 fi
    float p[BB];
    #pragma unroll
    for (int b = 0; b < BB; ++b) p[b] = 0.f;
    #pragma unroll
    for (int q = 0; q < 4; ++q) {
        int fi = q * 128 + t;
        const float* wp = row + fi * 9;
        float wsq = 0.f;
        #pragma unroll
        for (int k = 0; k < 9; ++k) { float v = wp[k]; wsq += v * v; }
        #pragma unroll
        for (int b = 0; b < BB; ++b) {
            float sv = g_s[b * FI + fi];
            p[b] += wsq * sv * sv;
        }
    }
    #pragma unroll
    for (int b = 0; b < BB; ++b) red[b][t] = p[b];
    __syncthreads();
    for (int off = 64; off > 0; off >>= 1) {
        if (t < off) {
            #pragma unroll
            for (int b = 0; b < BB; ++b)
                red[b][t] += red[b][t + off];
        }
        __syncthreads();
    }
    if (t < BB) {
        float sum = red[t][0] * (W_SCALE * W_SCALE) + EPSI;
        g_d[t * FO + fo] = rsqrtf(sum);
    }
}

// ---------------------------------------------------------------------------
// Kernel 3: xm = x*s, transposed to [b][r][c][fi], fp16 (half2 stores)
// ---------------------------------------------------------------------------
__global__ void k_xsplit(const float* __restrict__ x) {
    int b   = blockIdx.z;
    int r   = blockIdx.y;
    int fic = blockIdx.x * 64;
    __shared__ float tile[64][65];
    __shared__ float sv[64];
    int t = threadIdx.x;
    if (t < 64) sv[t] = g_s[b * FI + fic + t];
    #pragma unroll
    for (int i = 0; i < 16; ++i) {
        int idx = i * 256 + t;
        int fi = idx >> 6, c = idx & 63;
        tile[fi][c] = x[(((size_t)(b * FI + fic + fi)) * HH + r) * WW + c];
    }
    __syncthreads();
    __half2* outp = (__half2*)(g_xh + (((size_t)((b * HH + r) * WW)) << 9) + fic);
    #pragma unroll
    for (int i = 0; i < 8; ++i) {
        int idx = i * 256 + t;
        int c = idx >> 5, f2 = idx & 31;
        int fi = f2 * 2;
        float v0 = tile[fi][c]     * sv[fi];
        float v1 = tile[fi + 1][c] * sv[fi + 1];
        outp[(size_t)c * 256 + f2] = __floats2half2_rn(v0, v1);
    }
}

// ---------------------------------------------------------------------------
// Stage loader via cp.async (128 threads), hoisted per-thread bases
// ---------------------------------------------------------------------------
struct LoaderCtx {
    int rrA[4], ccA[4];
    const __half* srcA[4];
    uint32_t dstA[4];
    const __half* srcB[4];
    uint32_t dstB[4];
};

__device__ __forceinline__ void loader_init(LoaderCtx& L, int tid, int b,
                                            int r0, int foB) {
    #pragma unroll
    for (int p = 0; p < 4; ++p) {
        int slot = p * 128 + tid;
        int row = slot >> 2, jj = slot & 3;
        int rr = r0 + (row >> 6);
        int cc = row & 63;
        L.rrA[p] = rr; L.ccA[p] = cc;
        L.srcA[p] = g_xh + (((size_t)((b * HH + rr) * WW + cc)) << 9) + jj * 8;
        L.dstA[p] = (uint32_t)row * ROWB + jj * 16;
        L.srcB[p] = g_wh + (size_t)(foB + row) * KTOT + jj * 8;
        L.dstB[p] = (uint32_t)A_BYTES + (uint32_t)row * ROWB + jj * 16;
    }
}

__device__ __forceinline__ void load_stage(const LoaderCtx& L, int s, uint32_t smA) {
    int kk = s >> 4;
    int fc = (s & 15) << 5;
    int kd = kk / 3;
    int dr = kd - 1, dc = kk - kd * 3 - 1;
    const int adel = ((dr * WW + dc) << 9) + fc;   // A source delta (halves)
    const int bdel = s << 5;                        // B source delta (halves)
    #pragma unroll
    for (int p = 0; p < 4; ++p) {
        int rr = L.rrA[p] + dr, cc = L.ccA[p] + dc;
        int ok = ((unsigned)rr < (unsigned)HH) & ((unsigned)cc < (unsigned)WW);
        cp16(smA + L.dstA[p],
             ok ? (const void*)(L.srcA[p] + adel) : (const void*)g_xh,
             ok ? 16 : 0);
    }
    #pragma unroll
    for (int p = 0; p < 4; ++p)
        cp16(smA + L.dstB[p], L.srcB[p] + bdel, 16);
}

// ---------------------------------------------------------------------------
// Kernel 4: implicit-GEMM conv on mma.sync (single term, fp32 accum)
// CTA: M=128 px, N=128 fo; 4 warps, warp tile 64x64; 2 CTAs/SM; 5 stages.
// ---------------------------------------------------------------------------
__global__ void __launch_bounds__(128, 2)
k_conv_mma(float* __restrict__ y) {
    extern __shared__ char smem[];
    uint32_t sb = smem_u32(smem);
    const int tid = threadIdx.x;
    const int r0  = blockIdx.x * 2;
    const int foB = blockIdx.y * 128;
    const int b   = blockIdx.z;
    const int w   = tid >> 5, l = tid & 31;
    const int wm  = w & 1, wn = w >> 1;     // 2x2 warp grid, tile 64x64

    float acc[4][8][4];
    #pragma unroll
    for (int i = 0; i < 4; ++i)
        #pragma unroll
        for (int j = 0; j < 8; ++j)
            #pragma unroll
            for (int k = 0; k < 4; ++k) acc[i][j][k] = 0.f;

    LoaderCtx L;
    loader_init(L, tid, b, r0, foB);

    // prologue: stages 0..3
    load_stage(L, 0, sb);                   CP_COMMIT();
    load_stage(L, 1, sb + STAGE_BYTES);     CP_COMMIT();
    load_stage(L, 2, sb + 2 * STAGE_BYTES); CP_COMMIT();
    load_stage(L, 3, sb + 3 * STAGE_BYTES); CP_COMMIT();

    // ldmatrix address components (80B rows, no swizzle)
    uint32_t aoff[4];
    #pragma unroll
    for (int am = 0; am < 4; ++am) {
        int rowA = wm * 64 + am * 16 + (l & 15);
        aoff[am] = (uint32_t)rowA * ROWB;
    }
    const uint32_t acol = ((l >> 4) & 1) * 16;
    uint32_t boff[4];
    #pragma unroll
    for (int bp = 0; bp < 4; ++bp) {
        int rowB = wn * 64 + bp * 16 + ((l >> 4) << 3) + (l & 7);
        boff[bp] = (uint32_t)A_BYTES + (uint32_t)rowB * ROWB;
    }
    const uint32_t bcol = ((l >> 3) & 1) * 16;

    for (int s = 0; s < NCHUNK; ++s) {
        CP_WAIT3();
        __syncthreads();
        if (s + 4 < NCHUNK)
            load_stage(L, s + 4, sb + (uint32_t)((s + 4) % NSTG) * STAGE_BYTES);
        CP_COMMIT();

        uint32_t st = sb + (uint32_t)(s % NSTG) * STAGE_BYTES;
        uint32_t ah[2][4][4], bh[2][4][4];
        #pragma unroll
        for (int kst = 0; kst < 2; ++kst) {
            const uint32_t kb = (uint32_t)kst * 32;
            #pragma unroll
            for (int bp = 0; bp < 4; ++bp)
                LDSM4(bh[kst][bp], st + boff[bp] + bcol + kb);
            #pragma unroll
            for (int am = 0; am < 4; ++am)
                LDSM4(ah[kst][am], st + aoff[am] + acol + kb);
        }
        #pragma unroll
        for (int kst = 0; kst < 2; ++kst)
            #pragma unroll
            for (int am = 0; am < 4; ++am)
                #pragma unroll
                for (int bn = 0; bn < 8; ++bn) {
                    int bp = bn >> 1, h = (bn & 1) * 2;
                    mma16816(acc[am][bn], ah[kst][am], bh[kst][bp][h], bh[kst][bp][h + 1]);
                }
    }

    // epilogue: apply demod, streaming stores to NCHW
    const float* dp = g_d + b * FO + foB;
    const int mlow = l >> 2;
    #pragma unroll
    for (int am = 0; am < 4; ++am) {
        int m0 = wm * 64 + am * 16 + mlow;
        int rr0 = r0 + (m0 >> 6), cc0 = m0 & 63;
        int m1 = m0 + 8;
        int rr1 = r0 + (m1 >> 6), cc1 = m1 & 63;
        #pragma unroll
        for (int bn = 0; bn < 8; ++bn) {
            int n = wn * 64 + bn * 8 + (l & 3) * 2;
            float d0 = dp[n], d1 = dp[n + 1];
            float* p0 = y + ((size_t)((b * FO + foB + n)     * HH)) * WW;
            float* p1 = y + ((size_t)((b * FO + foB + n + 1) * HH)) * WW;
            stcs(p0 + (size_t)rr0 * WW + cc0, acc[am][bn][0] * d0);
            stcs(p1 + (size_t)rr0 * WW + cc0, acc[am][bn][1] * d1);
            stcs(p0 + (size_t)rr1 * WW + cc1, acc[am][bn][2] * d0);
            stcs(p1 + (size_t)rr1 * WW + cc1, acc[am][bn][3] * d1);
        }
    }
}

// ---------------------------------------------------------------------------
extern "C" void kernel_launch(void* const* d_in, const int* in_sizes, int n_in,
                              void* d_out, int out_size) {
    const float* x     = (const float*)d_in[0];
    const float* style = (const float*)d_in[1];
    const float* w     = (const float*)d_in[2];
    const float* fc_w  = (const float*)d_in[3];
    const float* fc_b  = (const float*)d_in[4];
    float* y = (float*)d_out;

    static bool attr_set = false;
    if (!attr_set) {
        cudaFuncSetAttribute(k_conv_mma, cudaFuncAttributeMaxDynamicSharedMemorySize, SMEM_TOTAL);
        attr_set = true;
    }

    k_style<<<BB, 256>>>(style, fc_w, fc_b);
    k_wd<<<FO, 128>>>(w);
    {
        dim3 g(FI / 64, HH, BB);   // (8, 64, 8)
        k_xsplit<<<g, 256>>>(x);
    }
    {
        dim3 g(HH / 2, FO / 128, BB);   // (32, 4, 8)
        k_conv_mma<<<g, 128, SMEM_TOTAL>>>(y);
    }
}

// round 16
// speedup vs baseline: 1.0251x; 1.0251x over previous
#include <cuda_runtime.h>
#include <cuda_fp16.h>
#include <cstdint>

// Problem constants
#define BB   8
#define FI   512
#define FO   512
#define HH   64
#define WW   64
#define DSTYLE 512
#define KTOT 4608                // 9 * 512

#define FC_SCALE 0.04419417382415922f      // 512^-0.5
#define W_SCALE  0.014731391274719739f     // (512*9)^-0.5
#define EPSI     1e-8f

// GEMM pipeline config: K-chunk 64, 3 stages, 2 CTAs/SM
#define NSTG        3
#define ROWB        144          // 128B data + 16B pad -> conflict-free ldmatrix, no swizzle
#define A_BYTES     (128*ROWB)   // 18432
#define B_BYTES     (128*ROWB)   // 18432
#define STAGE_BYTES (A_BYTES + B_BYTES)        // 36864
#define SMEM_TOTAL  (NSTG*STAGE_BYTES)         // 110592 per CTA (2 CTAs/SM = 221KB)
#define NCHUNK      72           // 9 kk * 8 fi-chunks of 64

// Scratch (device globals; no allocation allowed)
__device__ float  g_s[BB*FI];
__device__ float  g_d[BB*FO];
__device__ __half g_wh[(size_t)FO*KTOT];     // w_hi  [fo][kk*512+fi]
__device__ __half g_xh[(size_t)BB*HH*WW*FI]; // xm_hi [b][r][c][fi]

// ---------------------------------------------------------------------------
// helpers
// ---------------------------------------------------------------------------
__device__ __forceinline__ uint32_t smem_u32(const void* p){
    uint32_t a;
    asm("{ .reg .u64 t; cvta.to.shared.u64 t, %1; cvt.u32.u64 %0, t; }"
        : "=r"(a) : "l"(p));
    return a;
}
__device__ __forceinline__ void cp16(uint32_t dst, const void* src, int srcsz){
    asm volatile("cp.async.cg.shared.global [%0], [%1], 16, %2;"
                 :: "r"(dst), "l"(src), "r"(srcsz) : "memory");
}
#define CP_COMMIT() asm volatile("cp.async.commit_group;" ::: "memory")
#define CP_WAIT1()  asm volatile("cp.async.wait_group 1;" ::: "memory")

#define LDSM4(r, addr) \
    asm volatile("ldmatrix.sync.aligned.m8n8.x4.shared.b16 {%0,%1,%2,%3}, [%4];" \
        : "=r"((r)[0]),"=r"((r)[1]),"=r"((r)[2]),"=r"((r)[3]) : "r"(addr))

__device__ __forceinline__ void mma16816(float* c, const uint32_t* a,
                                         uint32_t b0, uint32_t b1){
    asm volatile("mma.sync.aligned.m16n8k16.row.col.f32.f16.f16.f32 "
        "{%0,%1,%2,%3}, {%4,%5,%6,%7}, {%8,%9}, {%0,%1,%2,%3};"
        : "+f"(c[0]),"+f"(c[1]),"+f"(c[2]),"+f"(c[3])
        : "r"(a[0]),"r"(a[1]),"r"(a[2]),"r"(a[3]), "r"(b0),"r"(b1));
}

// ---------------------------------------------------------------------------
// Kernel 1: s[b,i] = fc_b[i] + fc_scale * sum_j style[b,j] * fc_w[i,j]
// ---------------------------------------------------------------------------
__global__ void k_style(const float* __restrict__ style,
                        const float* __restrict__ fc_w,
                        const float* __restrict__ fc_b) {
    int b = blockIdx.x;
    __shared__ float st[DSTYLE];
    for (int j = threadIdx.x; j < DSTYLE; j += blockDim.x)
        st[j] = style[b * DSTYLE + j];
    __syncthreads();
    for (int i = threadIdx.x; i < FI; i += blockDim.x) {
        const float* wr = fc_w + (size_t)i * DSTYLE;
        float acc = 0.f;
        #pragma unroll 8
        for (int j = 0; j < DSTYLE; ++j) acc += st[j] * wr[j];
        g_s[b * FI + i] = acc * FC_SCALE + fc_b[i];
    }
}

// ---------------------------------------------------------------------------
// Kernel 2 (fused): per fo-row: coalesced w read, transposed fp16 write,
// demod reduction — one pass over w.
// ---------------------------------------------------------------------------
__global__ void k_wd(const float* __restrict__ w) {
    __shared__ float row[KTOT];              // 4608 floats = 18KB
    __shared__ float red[BB][128];
    int fo = blockIdx.x;
    int t  = threadIdx.x;                    // 128 threads
    const float* src = w + (size_t)fo * KTOT;
    for (int i = t; i < KTOT; i += 128)
        row[i] = src[i];
    __syncthreads();

    __half* dst = g_wh + (size_t)fo * KTOT;
    for (int i = t; i < KTOT; i += 128) {
        int kk = i >> 9, fi = i & 511;
        dst[i] = __float2half(row[fi * 9 + kk] * W_SCALE);
    }

    float p[BB];
    #pragma unroll
    for (int b = 0; b < BB; ++b) p[b] = 0.f;
    #pragma unroll
    for (int q = 0; q < 4; ++q) {
        int fi = q * 128 + t;
        const float* wp = row + fi * 9;
        float wsq = 0.f;
        #pragma unroll
        for (int k = 0; k < 9; ++k) { float v = wp[k]; wsq += v * v; }
        #pragma unroll
        for (int b = 0; b < BB; ++b) {
            float sv = g_s[b * FI + fi];
            p[b] += wsq * sv * sv;
        }
    }
    #pragma unroll
    for (int b = 0; b < BB; ++b) red[b][t] = p[b];
    __syncthreads();
    for (int off = 64; off > 0; off >>= 1) {
        if (t < off) {
            #pragma unroll
            for (int b = 0; b < BB; ++b)
                red[b][t] += red[b][t + off];
        }
        __syncthreads();
    }
    if (t < BB) {
        float sum = red[t][0] * (W_SCALE * W_SCALE) + EPSI;
        g_d[t * FO + fo] = rsqrtf(sum);
    }
}

// ---------------------------------------------------------------------------
// Kernel 3: xm = x*s, transposed to [b][r][c][fi], fp16 (half2 stores)
// ---------------------------------------------------------------------------
__global__ void k_xsplit(const float* __restrict__ x) {
    int b   = blockIdx.z;
    int r   = blockIdx.y;
    int fic = blockIdx.x * 64;
    __shared__ float tile[64][65];
    __shared__ float sv[64];
    int t = threadIdx.x;
    if (t < 64) sv[t] = g_s[b * FI + fic + t];
    #pragma unroll
    for (int i = 0; i < 16; ++i) {
        int idx = i * 256 + t;
        int fi = idx >> 6, c = idx & 63;
        tile[fi][c] = x[(((size_t)(b * FI + fic + fi)) * HH + r) * WW + c];
    }
    __syncthreads();
    __half2* outp = (__half2*)(g_xh + (((size_t)((b * HH + r) * WW)) << 9) + fic);
    #pragma unroll
    for (int i = 0; i < 8; ++i) {
        int idx = i * 256 + t;
        int c = idx >> 5, f2 = idx & 31;
        int fi = f2 * 2;
        float v0 = tile[fi][c]     * sv[fi];
        float v1 = tile[fi + 1][c] * sv[fi + 1];
        outp[(size_t)c * 256 + f2] = __floats2half2_rn(v0, v1);
    }
}

// ---------------------------------------------------------------------------
// Stage loader via cp.async (256 threads):
//   A[128 px][144B rows, 128B data];  B[128 fo][144B rows, 128B data]
// ---------------------------------------------------------------------------
__device__ __forceinline__ void load_stage(int s, int b, int r0, int foB,
                                           uint32_t smA, int tid) {
    int kk = s >> 3;
    int fc = (s & 7) << 6;                  // fi chunk base within kk (64 halves)
    int kd = kk / 3;
    int dr = kd - 1, dc = kk - kd * 3 - 1;
    uint32_t smB = smA + A_BYTES;
    const int bofs = s << 6;                // kk*512 + fc == 64*s (halves)
    // A: 1024 transfers of 16B, 4 per thread
    #pragma unroll
    for (int p = 0; p < 4; ++p) {
        int slot = p * 256 + tid;
        int row = slot >> 3, jj = slot & 7;
        int rr = r0 + (row >> 6) + dr;
        int cc = (row & 63) + dc;
        int ok = ((unsigned)rr < (unsigned)HH) & ((unsigned)cc < (unsigned)WW);
        int off = ok ? ((((b * HH + rr) * WW + cc) << 9) + fc + jj * 8) : 0;
        cp16(smA + row * ROWB + jj * 16, g_xh + off, ok ? 16 : 0);
    }
    // B: 1024 transfers of 16B, 4 per thread
    #pragma unroll
    for (int p = 0; p < 4; ++p) {
        int slot = p * 256 + tid;
        int fo = slot >> 3, jj = slot & 7;
        int off = (foB + fo) * KTOT + bofs + jj * 8;
        cp16(smB + fo * ROWB + jj * 16, g_wh + off, 16);
    }
}

// ---------------------------------------------------------------------------
// Kernel 4: implicit-GEMM conv on mma.sync (single term, fp32 accum)
// CTA: M=128 px, N=128 fo; 8 warps, warp tile 64x32; K-chunk 64; 3 stages.
// ---------------------------------------------------------------------------
__global__ void __launch_bounds__(256, 2)
k_conv_mma(float* __restrict__ y) {
    extern __shared__ char smem[];
    uint32_t sb = smem_u32(smem);
    const int tid = threadIdx.x;
    const int r0  = blockIdx.x * 2;
    const int foB = blockIdx.y * 128;
    const int b   = blockIdx.z;
    const int w   = tid >> 5, l = tid & 31;
    const int wm  = w >> 2, wn = w & 3;     // 2x4 warp grid, tile 64x32

    float acc[4][4][4];
    #pragma unroll
    for (int i = 0; i < 4; ++i)
        #pragma unroll
        for (int j = 0; j < 4; ++j)
            #pragma unroll
            for (int k = 0; k < 4; ++k) acc[i][j][k] = 0.f;

    // prologue: stages 0,1
    load_stage(0, b, r0, foB, sb, tid);               CP_COMMIT();
    load_stage(1, b, r0, foB, sb + STAGE_BYTES, tid); CP_COMMIT();

    // ldmatrix address components (144B rows, no swizzle needed)
    uint32_t aoff[4];
    #pragma unroll
    for (int am = 0; am < 4; ++am) {
        int rowA = wm * 64 + am * 16 + (l & 15);
        aoff[am] = (uint32_t)rowA * ROWB;
    }
    const uint32_t acol = ((l >> 4) & 1) * 16;
    uint32_t boff[2];
    #pragma unroll
    for (int bp = 0; bp < 2; ++bp) {
        int rowB = wn * 32 + bp * 16 + ((l >> 4) << 3) + (l & 7);
        boff[bp] = (uint32_t)A_BYTES + (uint32_t)rowB * ROWB;
    }
    const uint32_t bcol = ((l >> 3) & 1) * 16;

    for (int s = 0; s < NCHUNK; ++s) {
        CP_WAIT1();
        __syncthreads();
        if (s + 2 < NCHUNK)
            load_stage(s + 2, b, r0, foB,
                       sb + (uint32_t)((s + 2) % NSTG) * STAGE_BYTES, tid);
        CP_COMMIT();

        uint32_t st = sb + (uint32_t)(s % NSTG) * STAGE_BYTES;
        #pragma unroll
        for (int kst = 0; kst < 4; ++kst) {
            const uint32_t kb = (uint32_t)kst * 32;
            uint32_t ah[4][4], bh[2][4];
            #pragma unroll
            for (int bp = 0; bp < 2; ++bp)
                LDSM4(bh[bp], st + boff[bp] + bcol + kb);
            #pragma unroll
            for (int am = 0; am < 4; ++am)
                LDSM4(ah[am], st + aoff[am] + acol + kb);
            #pragma unroll
            for (int am = 0; am < 4; ++am)
                #pragma unroll
                for (int bn = 0; bn < 4; ++bn) {
                    int bp = bn >> 1, h = (bn & 1) * 2;
                    mma16816(acc[am][bn], ah[am], bh[bp][h], bh[bp][h + 1]);
                }
        }
    }

    // epilogue: apply demod, scatter to NCHW
    const float* dp = g_d + b * FO + foB;
    const int mlow = l >> 2;
    #pragma unroll
    for (int am = 0; am < 4; ++am) {
        int m0 = wm * 64 + am * 16 + mlow;
        int rr0 = r0 + (m0 >> 6), cc0 = m0 & 63;
        int m1 = m0 + 8;
        int rr1 = r0 + (m1 >> 6), cc1 = m1 & 63;
        #pragma unroll
        for (int bn = 0; bn < 4; ++bn) {
            int n = wn * 32 + bn * 8 + (l & 3) * 2;
            float d0 = dp[n], d1 = dp[n + 1];
            size_t base0 = ((size_t)((b * FO + foB + n)     * HH)) * WW;
            size_t base1 = ((size_t)((b * FO + foB + n + 1) * HH)) * WW;
            y[base0 + (size_t)rr0 * WW + cc0] = acc[am][bn][0] * d0;
            y[base1 + (size_t)rr0 * WW + cc0] = acc[am][bn][1] * d1;
            y[base0 + (size_t)rr1 * WW + cc1] = acc[am][bn][2] * d0;
            y[base1 + (size_t)rr1 * WW + cc1] = acc[am][bn][3] * d1;
        }
    }
}

// ---------------------------------------------------------------------------
extern "C" void kernel_launch(void* const* d_in, const int* in_sizes, int n_in,
                              void* d_out, int out_size) {
    const float* x     = (const float*)d_in[0];
    const float* style = (const float*)d_in[1];
    const float* w     = (const float*)d_in[2];
    const float* fc_w  = (const float*)d_in[3];
    const float* fc_b  = (const float*)d_in[4];
    float* y = (float*)d_out;

    static bool attr_set = false;
    if (!attr_set) {
        cudaFuncSetAttribute(k_conv_mma, cudaFuncAttributeMaxDynamicSharedMemorySize, SMEM_TOTAL);
        attr_set = true;
    }

    k_style<<<BB, 256>>>(style, fc_w, fc_b);
    k_wd<<<FO, 128>>>(w);
    {
        dim3 g(FI / 64, HH, BB);   // (8, 64, 8)
        k_xsplit<<<g, 256>>>(x);
    }
    {
        dim3 g(HH / 2, FO / 128, BB);   // (32, 4, 8)
        k_conv_mma<<<g, 256, SMEM_TOTAL>>>(y);
    }
}

// round 17
// speedup vs baseline: 1.1429x; 1.1149x over previous
#include <cuda_runtime.h>
#include <cuda_fp16.h>
#include <cstdint>

// Problem constants
#define BB   8
#define FI   512
#define FO   512
#define HH   64
#define WW   64
#define DSTYLE 512
#define KTOT 4608                // 9 * 512

#define FC_SCALE 0.04419417382415922f      // 512^-0.5
#define W_SCALE  0.014731391274719739f     // (512*9)^-0.5
#define EPSI     1e-8f

// Conv kernel config: A haloed (loaded once per fi-chunk), B 3-ring, K-chunk 64
#define ROWB     144             // 128B data + 16B pad (conflict-free ldmatrix)
#define A_ROWS   264             // (2+2) x 66 halo pixels
#define A_BYTES  (A_ROWS*ROWB)   // 38016
#define B_TILE   (128*ROWB)      // 18432
#define SMEM_TOTAL (A_BYTES + 3*B_TILE)   // 93312 -> 2 CTAs/SM
#define NITER    72              // 8 fi-chunks * 9 kk
#define A_OPS    (A_ROWS*8)      // 2112 cp16 per A tile

// Scratch (device globals; no allocation allowed)
__device__ float  g_s[BB*FI];
__device__ float  g_d[BB*FO];
__device__ __half g_wh[(size_t)FO*KTOT];     // w_hi  [fo][kk*512+fi]
__device__ __half g_xh[(size_t)BB*HH*WW*FI]; // xm_hi [b][r][c][fi]

// ---------------------------------------------------------------------------
// helpers
// ---------------------------------------------------------------------------
__device__ __forceinline__ uint32_t smem_u32(const void* p){
    uint32_t a;
    asm("{ .reg .u64 t; cvta.to.shared.u64 t, %1; cvt.u32.u64 %0, t; }"
        : "=r"(a) : "l"(p));
    return a;
}
__device__ __forceinline__ void cp16(uint32_t dst, const void* src, int srcsz){
    asm volatile("cp.async.cg.shared.global [%0], [%1], 16, %2;"
                 :: "r"(dst), "l"(src), "r"(srcsz) : "memory");
}
#define CP_COMMIT() asm volatile("cp.async.commit_group;" ::: "memory")
#define CP_WAIT0()  asm volatile("cp.async.wait_group 0;" ::: "memory")
#define CP_WAIT1()  asm volatile("cp.async.wait_group 1;" ::: "memory")

#define LDSM4(r, addr) \
    asm volatile("ldmatrix.sync.aligned.m8n8.x4.shared.b16 {%0,%1,%2,%3}, [%4];" \
        : "=r"((r)[0]),"=r"((r)[1]),"=r"((r)[2]),"=r"((r)[3]) : "r"(addr))

__device__ __forceinline__ void mma16816(float* c, const uint32_t* a,
                                         uint32_t b0, uint32_t b1){
    asm volatile("mma.sync.aligned.m16n8k16.row.col.f32.f16.f16.f32 "
        "{%0,%1,%2,%3}, {%4,%5,%6,%7}, {%8,%9}, {%0,%1,%2,%3};"
        : "+f"(c[0]),"+f"(c[1]),"+f"(c[2]),"+f"(c[3])
        : "r"(a[0]),"r"(a[1]),"r"(a[2]),"r"(a[3]), "r"(b0),"r"(b1));
}

// ---------------------------------------------------------------------------
// Kernel 1: s[b,i] = fc_b[i] + fc_scale * sum_j style[b,j] * fc_w[i,j]
// ---------------------------------------------------------------------------
__global__ void k_style(const float* __restrict__ style,
                        const float* __restrict__ fc_w,
                        const float* __restrict__ fc_b) {
    int b = blockIdx.x;
    __shared__ float st[DSTYLE];
    for (int j = threadIdx.x; j < DSTYLE; j += blockDim.x)
        st[j] = style[b * DSTYLE + j];
    __syncthreads();
    for (int i = threadIdx.x; i < FI; i += blockDim.x) {
        const float* wr = fc_w + (size_t)i * DSTYLE;
        float acc = 0.f;
        #pragma unroll 8
        for (int j = 0; j < DSTYLE; ++j) acc += st[j] * wr[j];
        g_s[b * FI + i] = acc * FC_SCALE + fc_b[i];
    }
}

// ---------------------------------------------------------------------------
// Kernel 2 (fused): per fo-row: coalesced w read, transposed fp16 write,
// demod reduction — one pass over w.
// ---------------------------------------------------------------------------
__global__ void k_wd(const float* __restrict__ w) {
    __shared__ float row[KTOT];              // 4608 floats = 18KB
    __shared__ float red[BB][128];
    int fo = blockIdx.x;
    int t  = threadIdx.x;                    // 128 threads
    const float* src = w + (size_t)fo * KTOT;
    for (int i = t; i < KTOT; i += 128)
        row[i] = src[i];
    __syncthreads();

    __half* dst = g_wh + (size_t)fo * KTOT;
    for (int i = t; i < KTOT; i += 128) {
        int kk = i >> 9, fi = i & 511;
        dst[i] = __float2half(row[fi * 9 + kk] * W_SCALE);
    }

    float p[BB];
    #pragma unroll
    for (int b = 0; b < BB; ++b) p[b] = 0.f;
    #pragma unroll
    for (int q = 0; q < 4; ++q) {
        int fi = q * 128 + t;
        const float* wp = row + fi * 9;
        float wsq = 0.f;
        #pragma unroll
        for (int k = 0; k < 9; ++k) { float v = wp[k]; wsq += v * v; }
        #pragma unroll
        for (int b = 0; b < BB; ++b) {
            float sv = g_s[b * FI + fi];
            p[b] += wsq * sv * sv;
        }
    }
    #pragma unroll
    for (int b = 0; b < BB; ++b) red[b][t] = p[b];
    __syncthreads();
    for (int off = 64; off > 0; off >>= 1) {
        if (t < off) {
            #pragma unroll
            for (int b = 0; b < BB; ++b)
                red[b][t] += red[b][t + off];
        }
        __syncthreads();
    }
    if (t < BB) {
        float sum = red[t][0] * (W_SCALE * W_SCALE) + EPSI;
        g_d[t * FO + fo] = rsqrtf(sum);
    }
}

// ---------------------------------------------------------------------------
// Kernel 3: xm = x*s, transposed to [b][r][c][fi], fp16 (half2 stores)
// ---------------------------------------------------------------------------
__global__ void k_xsplit(const float* __restrict__ x) {
    int b   = blockIdx.z;
    int r   = blockIdx.y;
    int fic = blockIdx.x * 64;
    __shared__ float tile[64][65];
    __shared__ float sv[64];
    int t = threadIdx.x;
    if (t < 64) sv[t] = g_s[b * FI + fic + t];
    #pragma unroll
    for (int i = 0; i < 16; ++i) {
        int idx = i * 256 + t;
        int fi = idx >> 6, c = idx & 63;
        tile[fi][c] = x[(((size_t)(b * FI + fic + fi)) * HH + r) * WW + c];
    }
    __syncthreads();
    __half2* outp = (__half2*)(g_xh + (((size_t)((b * HH + r) * WW)) << 9) + fic);
    #pragma unroll
    for (int i = 0; i < 8; ++i) {
        int idx = i * 256 + t;
        int c = idx >> 5, f2 = idx & 31;
        int fi = f2 * 2;
        float v0 = tile[fi][c]     * sv[fi];
        float v1 = tile[fi + 1][c] * sv[fi + 1];
        outp[(size_t)c * 256 + f2] = __floats2half2_rn(v0, v1);
    }
}

// ---------------------------------------------------------------------------
// Loaders (256 threads each). A: haloed 264x128B tile for one fi-chunk.
// B: 128 fo x 64 fi tile for one (fic,kk).
// ---------------------------------------------------------------------------
__device__ __forceinline__ void load_A(int fic, int b, int r0, uint32_t smA, int tid) {
    #pragma unroll
    for (int it = 0; it < 9; ++it) {
        int slot = it * 256 + tid;
        if (slot < A_OPS) {
            int row = slot >> 3, jj = slot & 7;
            int hr = row / 66, hc = row - hr * 66;
            int rr = r0 - 1 + hr, cc = hc - 1;
            int ok = ((unsigned)rr < (unsigned)HH) & ((unsigned)cc < (unsigned)WW);
            int off = ok ? ((((b * HH + rr) * WW + cc) << 9) + (fic << 6) + jj * 8) : 0;
            cp16(smA + row * ROWB + jj * 16, g_xh + off, ok ? 16 : 0);
        }
    }
    CP_COMMIT();
}

__device__ __forceinline__ void load_B(int i, int foB, uint32_t smB, int tid) {
    int fic = i / 9, kk = i - fic * 9;
    int kbase = (kk << 9) + (fic << 6);
    #pragma unroll
    for (int p = 0; p < 4; ++p) {
        int slot = p * 256 + tid;
        int fo = slot >> 3, jj = slot & 7;
        cp16(smB + fo * ROWB + jj * 16,
             g_wh + (size_t)(foB + fo) * KTOT + kbase + jj * 8, 16);
    }
    CP_COMMIT();
}

// ---------------------------------------------------------------------------
// Kernel 4: implicit-GEMM conv on mma.sync (single term, fp32 accum)
// CTA: M=128 px, N=128 fo; 8 warps 64x32; A haloed once/fi-chunk; kk inner.
// ---------------------------------------------------------------------------
__global__ void __launch_bounds__(256, 2)
k_conv_mma(float* __restrict__ y) {
    extern __shared__ char smem[];
    uint32_t sb = smem_u32(smem);
    const uint32_t smA = sb;
    const uint32_t smB0 = sb + A_BYTES;
    const int tid = threadIdx.x;
    const int r0  = blockIdx.x * 2;
    const int foB = blockIdx.y * 128;
    const int b   = blockIdx.z;
    const int w   = tid >> 5, l = tid & 31;
    const int wm  = w >> 2, wn = w & 3;     // 2x4 warp grid, tile 64x32

    float acc[4][4][4];
    #pragma unroll
    for (int i = 0; i < 4; ++i)
        #pragma unroll
        for (int j = 0; j < 4; ++j)
            #pragma unroll
            for (int k = 0; k < 4; ++k) acc[i][j][k] = 0.f;

    // ldmatrix address components
    uint32_t aoff[4];
    #pragma unroll
    for (int am = 0; am < 4; ++am) {
        int m = wm * 64 + am * 16 + (l & 15);
        int srow = ((m >> 6) + 1) * 66 + (m & 63) + 1;   // halo row
        aoff[am] = (uint32_t)srow * ROWB;
    }
    const uint32_t acol = ((l >> 4) & 1) * 16;
    uint32_t boff[2];
    #pragma unroll
    for (int bp = 0; bp < 2; ++bp) {
        int rowB = wn * 32 + bp * 16 + ((l >> 4) << 3) + (l & 7);
        boff[bp] = (uint32_t)rowB * ROWB;
    }
    const uint32_t bcol = ((l >> 3) & 1) * 16;

    // prologue: B0, B1 in flight
    load_B(0, foB, smB0, tid);
    load_B(1, foB, smB0 + B_TILE, tid);

    int bbuf = 0;                       // i % 3
    int kk = 0, fic = 0;
    for (int i = 0; i < NITER; ++i) {
        if (kk == 0) {
            // fi-chunk boundary: drain, load A(fic), keep B ring going
            CP_WAIT1();
            __syncthreads();            // A(fic-1) dead, B((i+2)%3) buffer dead
            load_A(fic, b, r0, smA, tid);
            if (i + 2 < NITER)
                load_B(i + 2, foB, smB0 + (uint32_t)((bbuf + 2) % 3) * B_TILE, tid);
            CP_WAIT0();                 // A ready (drains B pipeline too; 8x only)
            __syncthreads();
        } else {
            if (i == NITER - 1) CP_WAIT0(); else CP_WAIT1();
            __syncthreads();
            if (i + 2 < NITER)
                load_B(i + 2, foB, smB0 + (uint32_t)((bbuf + 2) % 3) * B_TILE, tid);
        }

        const int dr = kk / 3 - 1, dc = kk - (kk / 3) * 3 - 1;
        const int kkd = (dr * 66 + dc) * ROWB;         // uniform A shift for this tap
        const uint32_t st = smB0 + (uint32_t)bbuf * B_TILE;

        #pragma unroll
        for (int kst = 0; kst < 4; ++kst) {
            const uint32_t kb = (uint32_t)kst * 32;
            uint32_t ah[4][4], bh[2][4];
            #pragma unroll
            for (int bp = 0; bp < 2; ++bp)
                LDSM4(bh[bp], st + boff[bp] + bcol + kb);
            #pragma unroll
            for (int am = 0; am < 4; ++am)
                LDSM4(ah[am], smA + (uint32_t)((int)aoff[am] + kkd) + acol + kb);
            #pragma unroll
            for (int am = 0; am < 4; ++am)
                #pragma unroll
                for (int bn = 0; bn < 4; ++bn) {
                    int bp = bn >> 1, h = (bn & 1) * 2;
                    mma16816(acc[am][bn], ah[am], bh[bp][h], bh[bp][h + 1]);
                }
        }

        if (++kk == 9) { kk = 0; ++fic; }
        if (++bbuf == 3) bbuf = 0;
    }

    // epilogue: apply demod, scatter to NCHW
    const float* dp = g_d + b * FO + foB;
    const int mlow = l >> 2;
    #pragma unroll
    for (int am = 0; am < 4; ++am) {
        int m0 = wm * 64 + am * 16 + mlow;
        int rr0 = r0 + (m0 >> 6), cc0 = m0 & 63;
        int m1 = m0 + 8;
        int rr1 = r0 + (m1 >> 6), cc1 = m1 & 63;
        #pragma unroll
        for (int bn = 0; bn < 4; ++bn) {
            int n = wn * 32 + bn * 8 + (l & 3) * 2;
            float d0 = dp[n], d1 = dp[n + 1];
            size_t base0 = ((size_t)((b * FO + foB + n)     * HH)) * WW;
            size_t base1 = ((size_t)((b * FO + foB + n + 1) * HH)) * WW;
            y[base0 + (size_t)rr0 * WW + cc0] = acc[am][bn][0] * d0;
            y[base1 + (size_t)rr0 * WW + cc0] = acc[am][bn][1] * d1;
            y[base0 + (size_t)rr1 * WW + cc1] = acc[am][bn][2] * d0;
            y[base1 + (size_t)rr1 * WW + cc1] = acc[am][bn][3] * d1;
        }
    }
}

// ---------------------------------------------------------------------------
extern "C" void kernel_launch(void* const* d_in, const int* in_sizes, int n_in,
                              void* d_out, int out_size) {
    const float* x     = (const float*)d_in[0];
    const float* style = (const float*)d_in[1];
    const float* w     = (const float*)d_in[2];
    const float* fc_w  = (const float*)d_in[3];
    const float* fc_b  = (const float*)d_in[4];
    float* y = (float*)d_out;

    static bool attr_set = false;
    if (!attr_set) {
        cudaFuncSetAttribute(k_conv_mma, cudaFuncAttributeMaxDynamicSharedMemorySize, SMEM_TOTAL);
        attr_set = true;
    }

    k_style<<<BB, 256>>>(style, fc_w, fc_b);
    k_wd<<<FO, 128>>>(w);
    {
        dim3 g(FI / 64, HH, BB);   // (8, 64, 8)
        k_xsplit<<<g, 256>>>(x);
    }
    {
        dim3 g(HH / 2, FO / 128, BB);   // (32, 4, 8)
        k_conv_mma<<<g, 256, SMEM_TOTAL>>>(y);
    }
}